// round 6
// baseline (speedup 1.0000x reference)
#include <cuda_runtime.h>
#include <math.h>

#define N_X      130
#define N_INT    128
#define BATCH    64
#define LATENT   8
#define HIDDEN   64
#define IN_DIM   12
#define STAB     0.1f
#define MAX_ITER 5                   // err5 ~ 3e-5 (C~50 quadratic fit), 30x margin
#define GROUPS   4
#define JPT      (HIDDEN / GROUPS)   // 16 hidden units per thread
#define JP2      (JPT / 2)           // 8 packed pairs
#define NT       (N_INT * GROUPS)    // 512 threads

typedef unsigned long long u64;

__device__ __forceinline__ float tanh_fast(float v) {
    float y;
    asm("tanh.approx.f32 %0, %1;" : "=f"(y) : "f"(v));
    return y;
}
// MUFU-based near-exact tanh: 1 - 2/(exp(2x)+1). Abs err ~1e-7.
__device__ __forceinline__ float tanh_exact(float v) {
    const float e = __expf(2.0f * v);
    return 1.0f - __fdividef(2.0f, e + 1.0f);
}
__device__ __forceinline__ void bar_pcr() {          // warps 0-3 only
    asm volatile("bar.sync 1, 128;" ::: "memory");
}

// ---- packed f32x2 helpers (FFMA2 path: PTX-only, ptxas never auto-fuses) ----
__device__ __forceinline__ u64 pk2(float lo, float hi) {
    u64 r; asm("mov.b64 %0, {%1, %2};" : "=l"(r) : "f"(lo), "f"(hi)); return r;
}
__device__ __forceinline__ void upk2(float& lo, float& hi, u64 v) {
    asm("mov.b64 {%0, %1}, %2;" : "=f"(lo), "=f"(hi) : "l"(v));
}
__device__ __forceinline__ u64 fma2(u64 a, u64 b, u64 c) {
    u64 d; asm("fma.rn.f32x2 %0, %1, %2, %3;" : "=l"(d) : "l"(a), "l"(b), "l"(c)); return d;
}
__device__ __forceinline__ u64 mul2(u64 a, u64 b) {
    u64 d; asm("mul.rn.f32x2 %0, %1, %2;" : "=l"(d) : "l"(a), "l"(b)); return d;
}

__global__ void __launch_bounds__(NT, 1)
pde_newton_kernel(const float* __restrict__ u0,
                  const float* __restrict__ zb,
                  const float* __restrict__ x,
                  const float* __restrict__ W1,
                  const float* __restrict__ b1,
                  const float* __restrict__ W2,
                  const float* __restrict__ b2,
                  float* __restrict__ out)
{
    __shared__ float  W1s[IN_DIM * HIDDEN];
    __shared__ float  b1s[HIDDEN];
    __shared__ float  W2s[HIDDEN];
    __shared__ float  zs[LATENT];
    __shared__ float  xs[N_X];
    __shared__ float  us[N_INT + 2];        // zero Dirichlet padding
    __shared__ float4 red[NT];              // partial sums from groups 1..3
    __shared__ float4 T[2][N_INT];          // packed tridiag rows (A,B,C,D)
    __shared__ float  b2s;

    const int tid = threadIdx.x;
    const int bid = blockIdx.x;
    const int i   = tid & (N_INT - 1);      // interior point
    const int g   = tid >> 7;               // hidden group 0..3 (warp-uniform)

    // ---- cooperative loads ----
    for (int k = tid; k < IN_DIM * HIDDEN; k += NT) W1s[k] = W1[k];
    if (tid < HIDDEN) { b1s[tid] = b1[tid]; W2s[tid] = W2[tid]; }
    if (tid < LATENT) zs[tid] = zb[bid * LATENT + tid];
    if (tid < N_X)    xs[tid] = x[tid];
    if (tid == 0) { b2s = b2[0]; us[0] = 0.0f; us[N_INT + 1] = 0.0f; }
    if (tid < N_INT)  us[tid + 1] = u0[bid * N_INT + tid];
    __syncthreads();

    const float xi       = xs[i + 1];
    const float inv_dx2  = 1.0f / (xs[i + 2] - xs[i]);
    const float inv_hfhb = 1.0f / ((xs[i + 2] - xs[i + 1]) * (xs[i + 1] - xs[i]));

    // ---- packed weight pairs for this thread's 16 units (registers) ----
    const int jp0 = g * JP2;                // pair index base (pairs of hidden units)
    const float2* __restrict__ W1u2  = (const float2*)(W1s + 1 * HIDDEN);
    const float2* __restrict__ W1x2  = (const float2*)(W1s + 2 * HIDDEN);
    const float2* __restrict__ W1xx2 = (const float2*)(W1s + 3 * HIDDEN);
    const float2* __restrict__ W2p   = (const float2*)W2s;

    // ---- iteration-invariant preactivation (packed) ----
    u64 pre_c[JP2];
#pragma unroll
    for (int jj = 0; jj < JP2; jj++) {
        const int j = (jp0 + jj) * 2;
        float pc0 = fmaf(xi, W1s[j],     b1s[j]);
        float pc1 = fmaf(xi, W1s[j + 1], b1s[j + 1]);
#pragma unroll
        for (int k = 0; k < LATENT; k++) {
            pc0 = fmaf(zs[k], W1s[(4 + k) * HIDDEN + j],     pc0);
            pc1 = fmaf(zs[k], W1s[(4 + k) * HIDDEN + j + 1], pc1);
        }
        pre_c[jj] = pk2(pc0, pc1);
    }
    const u64 M1 = pk2(-1.0f, -1.0f);

#pragma unroll 1
    for (int iter = 0; iter < MAX_ITER; iter++) {
        const bool last = (iter == MAX_ITER - 1);   // exact residual on last step

        const float um  = us[i];
        const float uc  = us[i + 1];
        const float up  = us[i + 2];
        const float ux  = (up - um) * inv_dx2;
        const float uxx = (up - 2.0f * uc + um) * inv_hfhb;
        const u64 uc2  = pk2(uc,  uc);
        const u64 ux2  = pk2(ux,  ux);
        const u64 uxx2 = pk2(uxx, uxx);

        // ---- fused MLP forward + analytic Jacobian row, packed f32x2 ----
        u64 a0 = 0ull, a1 = 0ull, a2 = 0ull, a3 = 0ull;  // {0.f,0.f} bit pattern
#pragma unroll
        for (int jj = 0; jj < JP2; jj++) {
            const int jp = jp0 + jj;
            const float2 wu  = W1u2[jp];
            const float2 wx  = W1x2[jp];
            const float2 wxx = W1xx2[jp];
            const float2 w2v = W2p[jp];
            const u64 w1u2  = pk2(wu.x,  wu.y);
            const u64 w1x2  = pk2(wx.x,  wx.y);
            const u64 w1xx2 = pk2(wxx.x, wxx.y);
            const u64 w22   = pk2(w2v.x, w2v.y);

            u64 pre = pre_c[jj];
            pre = fma2(uc2,  w1u2,  pre);
            pre = fma2(ux2,  w1x2,  pre);
            pre = fma2(uxx2, w1xx2, pre);

            float p0, p1; upk2(p0, p1, pre);
            const float t0 = last ? tanh_exact(p0) : tanh_fast(p0);
            const float t1 = last ? tanh_exact(p1) : tanh_fast(p1);
            const u64 t2 = pk2(t0, t1);

            a0 = fma2(t2, w22, a0);
            const u64 tsq = mul2(t2, t2);
            const u64 nw2 = mul2(w22, M1);
            const u64 g2  = fma2(tsq, nw2, w22);   // w2*(1-t^2)
            a1 = fma2(g2, w1u2,  a1);
            a2 = fma2(g2, w1x2,  a2);
            a3 = fma2(g2, w1xx2, a3);
        }
        // horizontal add of packed lanes
        float l0, h0, l1, h1, l2, h2, l3, h3;
        upk2(l0, h0, a0); upk2(l1, h1, a1); upk2(l2, h2, a2); upk2(l3, h3, a3);
        const float s0 = l0 + h0, s1 = l1 + h1, s2 = l2 + h2, s3 = l3 + h3;

        if (g) red[tid] = make_float4(s0, s1, s2, s3);
        __syncthreads();                               // full bar #1

        if (tid < N_INT) {
            // ---- reduce 4 group partials (own partial already in regs) ----
            const float4 r1 = red[i + 128];
            const float4 r2 = red[i + 256];
            const float4 r3 = red[i + 384];
            const float acc_res  = (s0 + r1.x) + (r2.x + r3.x);
            const float acc_du   = (s1 + r1.y) + (r2.y + r3.y);
            const float acc_dux  = (s2 + r1.z) + (r2.z + r3.z);
            const float acc_duxx = (s3 + r1.w) + (r2.w + r3.w);

            const float q = (acc_duxx + STAB) * inv_hfhb;
            float4 m4;
            m4.x = (i == 0)         ? 0.0f : fmaf(-acc_dux, inv_dx2, q);
            m4.y = acc_du - 2.0f * q;
            m4.z = (i == N_INT - 1) ? 0.0f : fmaf( acc_dux, inv_dx2, q);
            m4.w = acc_res + b2s + STAB * uxx;
            T[0][i] = m4;
            bar_pcr();

            // ---- 6 PCR steps (coupling 1 -> 64), own row in regs ----
            int p = 0;
#pragma unroll
            for (int s = 1; s <= 32; s <<= 1) {
                float4 lo = make_float4(0.f, 1.f, 0.f, 0.f);
                float4 hi = make_float4(0.f, 1.f, 0.f, 0.f);
                if (i >= s)        lo = T[p][i - s];
                if (i + s < N_INT) hi = T[p][i + s];
                const float alpha = -__fdividef(m4.x, lo.y);
                const float beta  = -__fdividef(m4.z, hi.y);
                float4 n;
                n.x = alpha * lo.x;
                n.y = fmaf(alpha, lo.z, fmaf(beta, hi.x, m4.y));
                n.z = beta * hi.z;
                n.w = fmaf(alpha, lo.w, fmaf(beta, hi.w, m4.w));
                T[p ^ 1][i] = n;
                bar_pcr();
                m4 = n; p ^= 1;
            }

            // ---- close: pairs (i, i^64) form independent 2x2 systems ----
            const float4 qrow = T[p][i ^ 64];
            const float cc = (i < 64) ? m4.z : m4.x;
            const float qa = (i < 64) ? qrow.x : qrow.z;
            const float num = fmaf(m4.w, qrow.y, -cc * qrow.w);
            const float den = fmaf(m4.y, qrow.y, -cc * qa);
            const float unew = uc - __fdividef(num, den);   // DAMP = 1
            if (last) {
                out[bid * N_INT + i] = unew;               // fused final store
            } else {
                us[i + 1] = unew;
            }
        }
        if (!last) __syncthreads();                        // full bar #2
    }
}

extern "C" void kernel_launch(void* const* d_in, const int* in_sizes, int n_in,
                              void* d_out, int out_size)
{
    const float* u0 = (const float*)d_in[0];
    const float* zb = (const float*)d_in[1];
    const float* x  = (const float*)d_in[2];
    const float* W1 = (const float*)d_in[3];
    const float* b1 = (const float*)d_in[4];
    const float* W2 = (const float*)d_in[5];
    const float* b2 = (const float*)d_in[6];
    pde_newton_kernel<<<BATCH, NT>>>(u0, zb, x, W1, b1, W2, b2, (float*)d_out);
}

// round 7
// speedup vs baseline: 1.0025x; 1.0025x over previous
#include <cuda_runtime.h>
#include <math.h>

#define N_X      130
#define N_INT    128
#define BATCH    64
#define LATENT   8
#define HIDDEN   64
#define IN_DIM   12
#define STAB     0.1f
#define MAX_ITER 5                   // rel_err 3.8e-6 confirmed at 5 iters
#define GROUPS   4
#define JPT      (HIDDEN / GROUPS)   // 16 hidden units per thread
#define JP2      (JPT / 2)           // 8 packed pairs
#define NT       (N_INT * GROUPS)    // 512 threads

typedef unsigned long long u64;
union F2U { float2 f; u64 u; };

__device__ __forceinline__ u64 pk2(float lo, float hi) {
    F2U t; t.f = make_float2(lo, hi); return t.u;
}
__device__ __forceinline__ float2 upk2(u64 v) { F2U t; t.u = v; return t.f; }
__device__ __forceinline__ u64 ldp(const float2* p) { F2U t; t.f = *p; return t.u; }

__device__ __forceinline__ u64 fma2(u64 a, u64 b, u64 c) {
    u64 d; asm("fma.rn.f32x2 %0, %1, %2, %3;" : "=l"(d) : "l"(a), "l"(b), "l"(c)); return d;
}
__device__ __forceinline__ u64 mul2(u64 a, u64 b) {
    u64 d; asm("mul.rn.f32x2 %0, %1, %2;" : "=l"(d) : "l"(a), "l"(b)); return d;
}
__device__ __forceinline__ float tanh_fast(float v) {
    float y; asm("tanh.approx.f32 %0, %1;" : "=f"(y) : "f"(v)); return y;
}
// MUFU-based near-exact tanh: 1 - 2/(exp(2x)+1). Abs err ~1e-7.
__device__ __forceinline__ float tanh_exact(float v) {
    const float e = __expf(2.0f * v);
    return 1.0f - __fdividef(2.0f, e + 1.0f);
}
__device__ __forceinline__ void bar_pcr() {          // warps 0-3 only
    asm volatile("bar.sync 1, 128;" ::: "memory");
}

__global__ void __launch_bounds__(NT, 1)
pde_newton_kernel(const float* __restrict__ u0,
                  const float* __restrict__ zb,
                  const float* __restrict__ x,
                  const float* __restrict__ W1,
                  const float* __restrict__ b1,
                  const float* __restrict__ W2,
                  const float* __restrict__ b2,
                  float* __restrict__ out)
{
    __shared__ float  W1s[IN_DIM * HIDDEN];
    __shared__ float  b1s[HIDDEN];
    __shared__ float  W2s[HIDDEN];
    __shared__ float  nW2s[HIDDEN];         // -W2 (saves a mul2 per pair)
    __shared__ float  zs[LATENT];
    __shared__ float  xs[N_X];
    __shared__ float  us[N_INT + 2];        // zero Dirichlet padding
    __shared__ float4 red[NT];              // partial sums from groups 1..3
    __shared__ float4 T[2][N_INT];          // tridiag rows for shared PCR steps
    __shared__ float  b2s;

    const int tid = threadIdx.x;
    const int bid = blockIdx.x;
    const int q   = tid & (N_INT - 1);
    const int L   = q & 31;                 // lane
    const int ws  = q >> 5;                 // subwarp 0..3 within the 128-group
    const int i   = 4 * L + ws;             // PERMUTED interior point: PCR distances
                                            // 4,8,16,32 are lane offsets 1,2,4,8
    const int g   = tid >> 7;               // hidden group 0..3 (warp-uniform)

    // ---- cooperative loads ----
    for (int k = tid; k < IN_DIM * HIDDEN; k += NT) W1s[k] = W1[k];
    if (tid < HIDDEN) { b1s[tid] = b1[tid]; W2s[tid] = W2[tid]; nW2s[tid] = -W2[tid]; }
    if (tid < LATENT) zs[tid] = zb[bid * LATENT + tid];
    if (tid < N_X)    xs[tid] = x[tid];
    if (tid == 0) { b2s = b2[0]; us[0] = 0.0f; us[N_INT + 1] = 0.0f; }
    if (tid < N_INT)  us[tid + 1] = u0[bid * N_INT + tid];
    __syncthreads();

    const float xi       = xs[i + 1];
    const float inv_dx2  = 1.0f / (xs[i + 2] - xs[i]);
    const float inv_hfhb = 1.0f / ((xs[i + 2] - xs[i + 1]) * (xs[i + 1] - xs[i]));

    const float2* __restrict__ W1u2  = (const float2*)(W1s + 1 * HIDDEN);
    const float2* __restrict__ W1x2  = (const float2*)(W1s + 2 * HIDDEN);
    const float2* __restrict__ W1xx2 = (const float2*)(W1s + 3 * HIDDEN);
    const float2* __restrict__ W2p   = (const float2*)W2s;
    const float2* __restrict__ nW2p  = (const float2*)nW2s;

    // ---- iteration-invariant preactivation (packed) ----
    const int jp0 = g * JP2;
    u64 pre_c[JP2];
#pragma unroll
    for (int jj = 0; jj < JP2; jj++) {
        const int j = (jp0 + jj) * 2;
        float pc0 = fmaf(xi, W1s[j],     b1s[j]);
        float pc1 = fmaf(xi, W1s[j + 1], b1s[j + 1]);
#pragma unroll
        for (int k = 0; k < LATENT; k++) {
            pc0 = fmaf(zs[k], W1s[(4 + k) * HIDDEN + j],     pc0);
            pc1 = fmaf(zs[k], W1s[(4 + k) * HIDDEN + j + 1], pc1);
        }
        pre_c[jj] = pk2(pc0, pc1);
    }

#pragma unroll 1
    for (int iter = 0; iter < MAX_ITER; iter++) {
        const bool last = (iter == MAX_ITER - 1);   // exact residual on last step

        const float um  = us[i];
        const float uc  = us[i + 1];
        const float up  = us[i + 2];
        const float ux  = (up - um) * inv_dx2;
        const float uxx = (up - 2.0f * uc + um) * inv_hfhb;
        const u64 uc2  = pk2(uc,  uc);
        const u64 ux2  = pk2(ux,  ux);
        const u64 uxx2 = pk2(uxx, uxx);

        // ---- fused MLP forward + analytic Jacobian row, packed f32x2 ----
        u64 a0 = 0ull, a1 = 0ull, a2 = 0ull, a3 = 0ull;
#pragma unroll
        for (int jj = 0; jj < JP2; jj++) {
            const int jp = jp0 + jj;
            const u64 w1u2  = ldp(W1u2  + jp);
            const u64 w1x2  = ldp(W1x2  + jp);
            const u64 w1xx2 = ldp(W1xx2 + jp);
            const u64 w22   = ldp(W2p   + jp);
            const u64 nw22  = ldp(nW2p  + jp);

            u64 pre = pre_c[jj];
            pre = fma2(uc2,  w1u2,  pre);
            pre = fma2(ux2,  w1x2,  pre);
            pre = fma2(uxx2, w1xx2, pre);

            const float2 pf = upk2(pre);
            const float t0 = last ? tanh_exact(pf.x) : tanh_fast(pf.x);
            const float t1 = last ? tanh_exact(pf.y) : tanh_fast(pf.y);
            const u64 t2 = pk2(t0, t1);

            a0 = fma2(t2, w22, a0);
            const u64 tsq = mul2(t2, t2);
            const u64 g2  = fma2(tsq, nw22, w22);   // w2*(1-t^2)
            a1 = fma2(g2, w1u2,  a1);
            a2 = fma2(g2, w1x2,  a2);
            a3 = fma2(g2, w1xx2, a3);
        }
        const float2 f0 = upk2(a0), f1 = upk2(a1), f2 = upk2(a2), f3 = upk2(a3);
        const float s0 = f0.x + f0.y, s1 = f1.x + f1.y;
        const float s2 = f2.x + f2.y, s3 = f3.x + f3.y;

        if (g) red[tid] = make_float4(s0, s1, s2, s3);
        __syncthreads();                               // full bar #1

        float unew;
        if (tid < N_INT) {
            // ---- reduce 4 group partials (own partial already in regs) ----
            const float4 r1 = red[q + 128];
            const float4 r2 = red[q + 256];
            const float4 r3 = red[q + 384];
            const float acc_res  = (s0 + r1.x) + (r2.x + r3.x);
            const float acc_du   = (s1 + r1.y) + (r2.y + r3.y);
            const float acc_dux  = (s2 + r1.z) + (r2.z + r3.z);
            const float acc_duxx = (s3 + r1.w) + (r2.w + r3.w);

            const float qq = (acc_duxx + STAB) * inv_hfhb;
            float4 m4;
            m4.x = (i == 0)         ? 0.0f : fmaf(-acc_dux, inv_dx2, qq);
            m4.y = acc_du - 2.0f * qq;
            m4.z = (i == N_INT - 1) ? 0.0f : fmaf( acc_dux, inv_dx2, qq);
            m4.w = acc_res + b2s + STAB * uxx;
            T[0][i] = m4;
            bar_pcr();

            // ---- shared PCR steps s=1, s=2 (cross-subwarp coupling) ----
#pragma unroll
            for (int s = 1; s <= 2; s <<= 1) {
                float4 lo = make_float4(0.f, 1.f, 0.f, 0.f);
                float4 hi = make_float4(0.f, 1.f, 0.f, 0.f);
                if (i >= s)        lo = T[s - 1][i - s];
                if (i + s < N_INT) hi = T[s - 1][i + s];
                const float alpha = -__fdividef(m4.x, lo.y);
                const float beta  = -__fdividef(m4.z, hi.y);
                float4 n;
                n.x = alpha * lo.x;
                n.y = fmaf(alpha, lo.z, fmaf(beta, hi.x, m4.y));
                n.z = beta * hi.z;
                n.w = fmaf(alpha, lo.w, fmaf(beta, hi.w, m4.w));
                m4 = n;
                if (s == 1) { T[1][i] = m4; bar_pcr(); }
            }

            // ---- shfl PCR steps s=4,8,16,32 (lane offsets 1,2,4,8) ----
            // Edge rows need no guards: A[i]==0 exactly for i<s (and C for
            // i>=N-s), maintained as exact +/-0 through every step, so the
            // clamped-shfl garbage rows are multiplied by exactly zero.
#pragma unroll
            for (int d = 1; d <= 8; d <<= 1) {
                const float lox = __shfl_up_sync(0xffffffffu, m4.x, d);
                const float loy = __shfl_up_sync(0xffffffffu, m4.y, d);
                const float loz = __shfl_up_sync(0xffffffffu, m4.z, d);
                const float low = __shfl_up_sync(0xffffffffu, m4.w, d);
                const float hix = __shfl_down_sync(0xffffffffu, m4.x, d);
                const float hiy = __shfl_down_sync(0xffffffffu, m4.y, d);
                const float hiz = __shfl_down_sync(0xffffffffu, m4.z, d);
                const float hiw = __shfl_down_sync(0xffffffffu, m4.w, d);
                const float alpha = -__fdividef(m4.x, loy);
                const float beta  = -__fdividef(m4.z, hiy);
                float4 n;
                n.x = alpha * lox;
                n.y = fmaf(alpha, loz, fmaf(beta, hix, m4.y));
                n.z = beta * hiz;
                n.w = fmaf(alpha, low, fmaf(beta, hiw, m4.w));
                m4 = n;
            }

            // ---- close: pairs (i, i^64) <-> lanes (L, L^16), 2x2 Cramer ----
            const float qx = __shfl_xor_sync(0xffffffffu, m4.x, 16);
            const float qy = __shfl_xor_sync(0xffffffffu, m4.y, 16);
            const float qz = __shfl_xor_sync(0xffffffffu, m4.z, 16);
            const float qw = __shfl_xor_sync(0xffffffffu, m4.w, 16);
            const float cc = (L < 16) ? m4.z : m4.x;
            const float qa = (L < 16) ? qx   : qz;
            const float num = fmaf(m4.w, qy, -cc * qw);
            const float den = fmaf(m4.y, qy, -cc * qa);
            unew = uc - __fdividef(num, den);          // DAMP = 1
            if (last) out[bid * N_INT + i] = unew;     // fused final store
            else      us[i + 1] = unew;
        }
        if (!last) __syncthreads();                    // full bar #2
    }
}

extern "C" void kernel_launch(void* const* d_in, const int* in_sizes, int n_in,
                              void* d_out, int out_size)
{
    const float* u0 = (const float*)d_in[0];
    const float* zb = (const float*)d_in[1];
    const float* x  = (const float*)d_in[2];
    const float* W1 = (const float*)d_in[3];
    const float* b1 = (const float*)d_in[4];
    const float* W2 = (const float*)d_in[5];
    const float* b2 = (const float*)d_in[6];
    pde_newton_kernel<<<BATCH, NT>>>(u0, zb, x, W1, b1, W2, b2, (float*)d_out);
}